// round 7
// baseline (speedup 1.0000x reference)
#include <cuda_runtime.h>
#include <cuda_bf16.h>
#include <cstdint>
#include <math.h>

// ---------------- problem constants ----------------
#define CAMS   4
#define DSLICE 4      // D = NDISP/2
#define NDISP  8
#define IH     640
#define IW     1280
#define FH     320
#define FW     640
#define C1     32
#define HO     256
#define WO     256
#define CF     128    // fused cost channels
#define C2     64
#define C3     32

#define PK1    (CF + 8)    // padded K (elements) conv1
#define PK2    (C2 + 8)    // padded K conv2

// ---------------- scratch (static device memory; no allocs) ----------------
__device__ float g_feat [(size_t)CAMS*FH*FW*C1];              // [cam][y][x][c]
__device__ float g_warp [(size_t)CAMS*DSLICE*FH*FW*C1];       // [cam][d][y][x][c]
__device__ __nv_bfloat16 g_costs_h[(size_t)DSLICE*HO*WO*CF];  // hi plane, [d][h][w][c]
__device__ __nv_bfloat16 g_costs_l[(size_t)DSLICE*HO*WO*CF];  // lo plane
__device__ __nv_bfloat16 g_x1_h  [(size_t)DSLICE*HO*WO*C2];
__device__ __nv_bfloat16 g_x1_l  [(size_t)DSLICE*HO*WO*C2];
__device__ float g_x2   [(size_t)DSLICE*HO*WO*C3];
__device__ float g_x3   [(size_t)DSLICE*HO*WO];
__device__ __nv_bfloat16 g_wB1[27*2*C2*PK1];   // [tap][hi/lo][n][PK1]
__device__ __nv_bfloat16 g_wB2[27*2*C3*PK2];   // [tap][hi/lo][n][PK2]

// =====================================================================
// helpers
// =====================================================================
__device__ __forceinline__ uint32_t smem_u32(const void* p) {
    uint32_t a;
    asm("{ .reg .u64 t; cvta.to.shared.u64 t, %1; cvt.u32.u64 %0, t; }" : "=r"(a) : "l"(p));
    return a;
}
__device__ __forceinline__ uint32_t lds32(uint32_t addr) {
    uint32_t r;
    asm volatile("ld.shared.b32 %0, [%1];" : "=r"(r) : "r"(addr));
    return r;
}
__device__ __forceinline__ void lds128f(uint32_t addr, float& a, float& b, float& c, float& d) {
    asm volatile("ld.shared.v4.f32 {%0,%1,%2,%3}, [%4];"
                 : "=f"(a), "=f"(b), "=f"(c), "=f"(d) : "r"(addr));
}
__device__ __forceinline__ void sts128f(uint32_t addr, float a, float b, float c, float d) {
    asm volatile("st.shared.v4.f32 [%0], {%1,%2,%3,%4};"
                 :: "r"(addr), "f"(a), "f"(b), "f"(c), "f"(d) : "memory");
}
__device__ __forceinline__ void cp_async16(uint32_t dst, const void* src, bool valid) {
    int sz = valid ? 16 : 0;
    asm volatile("cp.async.cg.shared.global [%0], [%1], 16, %2;"
                 :: "r"(dst), "l"(src), "r"(sz) : "memory");
}
__device__ __forceinline__ void cp_commit() {
    asm volatile("cp.async.commit_group;" ::: "memory");
}
__device__ __forceinline__ void cp_wait1() {
    asm volatile("cp.async.wait_group 1;" ::: "memory");
}
__device__ __forceinline__ void cp_wait0() {
    asm volatile("cp.async.wait_group 0;" ::: "memory");
}
__device__ __forceinline__ void mma_bf16(float& d0, float& d1, float& d2, float& d3,
                                         uint32_t a0, uint32_t a1, uint32_t a2, uint32_t a3,
                                         uint32_t b0, uint32_t b1)
{
    asm volatile(
        "mma.sync.aligned.m16n8k16.row.col.f32.bf16.bf16.f32 "
        "{%0,%1,%2,%3}, {%4,%5,%6,%7}, {%8,%9}, {%0,%1,%2,%3};"
        : "+f"(d0), "+f"(d1), "+f"(d2), "+f"(d3)
        : "r"(a0), "r"(a1), "r"(a2), "r"(a3), "r"(b0), "r"(b1));
}
// pack two floats into bf16x2 hi pair + residual bf16x2 lo pair
__device__ __forceinline__ void split2(float x0, float x1, uint32_t& hi, uint32_t& lo)
{
    __nv_bfloat16 h0 = __float2bfloat16(x0);
    __nv_bfloat16 h1 = __float2bfloat16(x1);
    float r0 = x0 - __bfloat162float(h0);
    float r1 = x1 - __bfloat162float(h1);
    __nv_bfloat162 hp = __halves2bfloat162(h0, h1);
    __nv_bfloat162 lp = __halves2bfloat162(__float2bfloat16(r0), __float2bfloat16(r1));
    hi = *(uint32_t*)&hp;
    lo = *(uint32_t*)&lp;
}

// ---------------- K1: conv2d 3->32 s2 + relu (grid.z<4) fused with weight prep (grid.z==4) ----
__global__ void k_feat4w(const float* __restrict__ c0, const float* __restrict__ c1,
                         const float* __restrict__ c2, const float* __restrict__ c3,
                         const float* __restrict__ w,
                         const float* __restrict__ w_fusion, const float* __restrict__ w_reg1)
{
    int tid = threadIdx.y * 16 + threadIdx.x;
    int zi  = blockIdx.z;

    if (zi == 4) {
        // ---- weight prep: bf16 hi/lo B images [tap][hi/lo][n][PK] ----
        int idx0   = (blockIdx.y * (FW / 16) + blockIdx.x) * 256 + tid;
        int stride = (FW / 16) * (FH / 16) * 256;     // 204800
        for (int i = idx0; i < 27 * C2 * CF; i += stride) {
            int k = i % CF;
            int n = (i / CF) % C2;
            int t = i / (CF * C2);
            int kw = t % 3, kh = (t / 3) % 3, kd = t / 9;
            float v = w_fusion[((((size_t)n * CF + k) * 3 + kd) * 3 + kh) * 3 + kw];
            __nv_bfloat16 h = __float2bfloat16(v);
            __nv_bfloat16 l = __float2bfloat16(v - __bfloat162float(h));
            g_wB1[((size_t)(t * 2 + 0) * C2 + n) * PK1 + k] = h;
            g_wB1[((size_t)(t * 2 + 1) * C2 + n) * PK1 + k] = l;
        }
        for (int i = idx0; i < 27 * C3 * C2; i += stride) {
            int k = i % C2;
            int n = (i / C2) % C3;
            int t = i / (C2 * C3);
            int kw = t % 3, kh = (t / 3) % 3, kd = t / 9;
            float v = w_reg1[((((size_t)n * C2 + k) * 3 + kd) * 3 + kh) * 3 + kw];
            __nv_bfloat16 h = __float2bfloat16(v);
            __nv_bfloat16 l = __float2bfloat16(v - __bfloat162float(h));
            g_wB2[((size_t)(t * 2 + 0) * C3 + n) * PK2 + k] = h;
            g_wB2[((size_t)(t * 2 + 1) * C3 + n) * PK2 + k] = l;
        }
        return;
    }

    __shared__ float ws[27 * 32];
    for (int i = tid; i < 864; i += 256) {
        int k = i >> 5, oc = i & 31;
        ws[i] = w[oc * 27 + k];
    }
    __syncthreads();

    const float* cam = (zi == 0) ? c0 : (zi == 1) ? c1 : (zi == 2) ? c2 : c3;
    int ow = blockIdx.x * 16 + threadIdx.x;
    int oh = blockIdx.y * 16 + threadIdx.y;

    float v[27];
#pragma unroll
    for (int ic = 0; ic < 3; ic++)
#pragma unroll
        for (int kh = 0; kh < 3; kh++)
#pragma unroll
            for (int kw = 0; kw < 3; kw++) {
                int iy = 2 * oh + kh - 1;
                int ix = 2 * ow + kw - 1;
                float t = 0.f;
                if (iy >= 0 && iy < IH && ix >= 0 && ix < IW)
                    t = cam[(size_t)ic * IH * IW + (size_t)iy * IW + ix];
                v[ic * 9 + kh * 3 + kw] = t;
            }

    float4 acc[8];
#pragma unroll
    for (int q = 0; q < 8; q++) acc[q] = make_float4(0.f, 0.f, 0.f, 0.f);
    const float4* ws4 = (const float4*)ws;
#pragma unroll
    for (int k = 0; k < 27; k++) {
        float vv = v[k];
#pragma unroll
        for (int q = 0; q < 8; q++) {
            float4 wv = ws4[k * 8 + q];
            acc[q].x += vv * wv.x;  acc[q].y += vv * wv.y;
            acc[q].z += vv * wv.z;  acc[q].w += vv * wv.w;
        }
    }
    float4* o = (float4*)(g_feat + ((size_t)zi * FH * FW + (size_t)oh * FW + ow) * C1);
#pragma unroll
    for (int q = 0; q < 8; q++) {
        float4 r = acc[q];
        r.x = fmaxf(r.x, 0.f); r.y = fmaxf(r.y, 0.f);
        r.z = fmaxf(r.z, 0.f); r.w = fmaxf(r.w, 0.f);
        o[q] = r;
    }
}

// ---------------- K2: grid_sample, warp-cooperative, 2 d-slices per thread (MLP x2) -----------
__global__ void __launch_bounds__(256)
k_warp(const float* __restrict__ grids)
{
    int tid = threadIdx.x;
    int c   = tid & 7;           // channel chunk (4 floats)
    int pid = tid >> 3;          // pixel within block (0..31)
    int pos = blockIdx.x * 32 + pid;
    int d0  = blockIdx.y;        // 0..1 -> handles d0 and d0+2
    int cam = blockIdx.z;
    int y = pos / FW, x = pos % FW;

    const float* fb = g_feat + (size_t)cam * FH * FW * C1 + c * 4;

#pragma unroll
    for (int s = 0; s < 2; s++) {
        int d = d0 + s * 2;
        const float* g = grids + ((((size_t)cam * DSLICE + d) * FH + y) * FW + x) * 2;
        float fx = (g[0] + 1.f) * (FW * 0.5f) - 0.5f;
        float fy = (g[1] + 1.f) * (FH * 0.5f) - 0.5f;
        float x0f = floorf(fx), y0f = floorf(fy);
        float wx = fx - x0f,   wy = fy - y0f;
        int x0 = (int)x0f, y0 = (int)y0f;
        int x1 = x0 + 1,   y1 = y0 + 1;
        float vx0 = (x0 >= 0 && x0 < FW) ? 1.f : 0.f;
        float vx1 = (x1 >= 0 && x1 < FW) ? 1.f : 0.f;
        float vy0 = (y0 >= 0 && y0 < FH) ? 1.f : 0.f;
        float vy1 = (y1 >= 0 && y1 < FH) ? 1.f : 0.f;
        float w00 = (1.f - wx) * (1.f - wy) * vx0 * vy0;
        float w01 = wx * (1.f - wy) * vx1 * vy0;
        float w10 = (1.f - wx) * wy * vx0 * vy1;
        float w11 = wx * wy * vx1 * vy1;
        int x0c = min(max(x0, 0), FW - 1), x1c = min(max(x1, 0), FW - 1);
        int y0c = min(max(y0, 0), FH - 1), y1c = min(max(y1, 0), FH - 1);

        float4 a = *(const float4*)(fb + ((size_t)y0c * FW + x0c) * C1);
        float4 b = *(const float4*)(fb + ((size_t)y0c * FW + x1c) * C1);
        float4 e = *(const float4*)(fb + ((size_t)y1c * FW + x0c) * C1);
        float4 f = *(const float4*)(fb + ((size_t)y1c * FW + x1c) * C1);

        float4 r;
        r.x = w00 * a.x + w01 * b.x + w10 * e.x + w11 * f.x;
        r.y = w00 * a.y + w01 * b.y + w10 * e.y + w11 * f.y;
        r.z = w00 * a.z + w01 * b.z + w10 * e.z + w11 * f.z;
        r.w = w00 * a.w + w01 * b.w + w10 * e.w + w11 * f.w;
        *(float4*)(g_warp + ((size_t)(cam * DSLICE + d) * FH * FW + pos) * C1 + c * 4) = r;
    }
}

// ---------------- K3: antialiased resize, warp-cooperative, bf16 hi/lo output ----------------
__global__ void __launch_bounds__(256)
k_resize()
{
    int tid  = threadIdx.x;
    int c    = tid & 7;
    int pid  = tid >> 3;
    int opos = blockIdx.x * 32 + pid;
    int ho   = opos >> 8;
    int wo   = opos & 255;
    int d    = blockIdx.y;
    int cam  = blockIdx.z;

    float sy = (ho + 0.5f) * 1.25f - 0.5f;
    int jy0 = max((int)ceilf(sy - 1.25f), 0);
    int jy1 = min((int)floorf(sy + 1.25f), FH - 1);
    float wyv[4]; int ny = jy1 - jy0 + 1;
    float sumy = 0.f;
    for (int i = 0; i < ny; i++) {
        float w = fmaxf(1.f - fabsf(sy - (float)(jy0 + i)) * 0.8f, 0.f);
        wyv[i] = w; sumy += w;
    }
    for (int i = 0; i < ny; i++) wyv[i] /= sumy;

    float sx = (wo + 0.5f) * 2.5f - 0.5f;
    int jx0 = max((int)ceilf(sx - 2.5f), 0);
    int jx1 = min((int)floorf(sx + 2.5f), FW - 1);
    float wxv[6]; int nx = jx1 - jx0 + 1;
    float sumx = 0.f;
    for (int i = 0; i < nx; i++) {
        float w = fmaxf(1.f - fabsf(sx - (float)(jx0 + i)) * 0.4f, 0.f);
        wxv[i] = w; sumx += w;
    }
    for (int i = 0; i < nx; i++) wxv[i] /= sumx;

    float4 acc = make_float4(0.f, 0.f, 0.f, 0.f);
    const float* base = g_warp + (size_t)(cam * DSLICE + d) * FH * FW * C1 + c * 4;
    for (int iy = 0; iy < ny; iy++) {
        const float* rowb = base + (size_t)(jy0 + iy) * FW * C1;
        for (int ix = 0; ix < nx; ix++) {
            float wgt = wyv[iy] * wxv[ix];
            float4 t = *(const float4*)(rowb + (size_t)(jx0 + ix) * C1);
            acc.x += wgt * t.x; acc.y += wgt * t.y;
            acc.z += wgt * t.z; acc.w += wgt * t.w;
        }
    }
    size_t obase = (((size_t)d * HO + ho) * WO + wo) * CF + cam * C1 + c * 4;
    uint32_t h0, l0, h1, l1;
    split2(acc.x, acc.y, h0, l0);
    split2(acc.z, acc.w, h1, l1);
    *(uint2*)(g_costs_h + obase) = make_uint2(h0, h1);
    *(uint2*)(g_costs_l + obase) = make_uint2(l0, l1);
}

// ---------------- K4: conv3d 3x3x3 pad1 + relu, mma.sync bf16 split, K-split warps ----------
// 256 threads / 8 warps: 2 K-halves x (M,N) tiles. Warp tile (MI*16) x 32, K = CIN/2 per warp.
// conv1: MI=4 (2 M-tiles x 2 N-tiles x 2 K). conv2: MI=2 (4 M-tiles x 1 N-tile x 2 K).
template<int CIN, int COUT, int MI, bool OBF>
__global__ void __launch_bounds__(256)
k_conv3d_mma(const __nv_bfloat16* __restrict__ in_h, const __nv_bfloat16* __restrict__ in_l,
             const __nv_bfloat16* __restrict__ wB,
             __nv_bfloat16* __restrict__ out_h, __nv_bfloat16* __restrict__ out_l,
             float* __restrict__ out_f)
{
    constexpr int NT   = 256;
    constexpr int PK   = CIN + 8;
    constexpr int PKB  = PK * 2;             // bytes per smem row
    constexpr int SA   = 130 * PKB;          // one A plane (hi or lo)
    constexpr int AB   = 2 * SA;             // A buffer (hi + lo)
    constexpr int TB   = 2 * COUT * PKB;     // one B tap (hi + lo)
    constexpr int NTN  = COUT / 32;          // N tiles
    constexpr int KS   = CIN / 32;           // per-warp 16-elem K steps
    constexpr int CH   = CIN / 8;            // 16B chunks per A row per plane

    extern __shared__ char dsm[];
    const uint32_t sBase = smem_u32(dsm);
    const uint32_t sA0 = sBase;              // [A0 | A1 | B0 | B1]
    const uint32_t sB0 = sBase + 2 * AB;

    int tid  = threadIdx.x;
    int wid  = tid >> 5, lane = tid & 31;
    int gid  = lane >> 2, tig = lane & 3;
    int wK   = wid & 1;                      // K half
    int wmn  = wid >> 1;                     // 0..3
    int wM   = wmn / NTN;
    int wN   = wmn % NTN;
    int ow0  = blockIdx.x * 128;
    int oh   = blockIdx.y, od = blockIdx.z;

    // ---- build valid (kd,kh) list ----
    int zdv[9], zhv[9], t9v[9];
    int nv = 0;
    for (int kd = 0; kd < 3; kd++) {
        int zd = od + kd - 1;
        if (zd < 0 || zd >= DSLICE) continue;
        for (int kh = 0; kh < 3; kh++) {
            int zh = oh + kh - 1;
            if (zh < 0 || zh >= HO) continue;
            zdv[nv] = zd; zhv[nv] = zh; t9v[nv] = kd * 3 + kh;
            nv++;
        }
    }
    int nitems = nv * 3;

    float acc[MI][4][4];
#pragma unroll
    for (int mi = 0; mi < MI; mi++)
#pragma unroll
        for (int nj = 0; nj < 4; nj++)
#pragma unroll
            for (int cc = 0; cc < 4; cc++) acc[mi][nj][cc] = 0.f;

    auto stage_A = [&](int slot, int ai) {
        size_t inoff = ((size_t)zdv[ai] * HO + zhv[ai]) * WO * CIN;
        uint32_t dA = sA0 + slot * AB;
        for (int i = tid; i < 130 * CH; i += NT) {
            int r = i / CH, g = i % CH;
            int p = ow0 - 1 + r;
            bool v = (p >= 0 && p < WO);
            int pc = v ? p : 0;
            size_t so = inoff + (size_t)pc * CIN + g * 8;
            uint32_t doff = (uint32_t)r * PKB + g * 16;
            cp_async16(dA + doff,      in_h + so, v);
            cp_async16(dA + SA + doff, in_l + so, v);
        }
    };
    auto stage_B = [&](int slot, int j) {
        int t = t9v[j / 3] * 3 + (j % 3);
        const char* src = (const char*)(wB + (size_t)t * COUT * PK * 2);
        uint32_t dB = sB0 + slot * TB;
        for (int i = tid; i < TB / 16; i += NT)
            cp_async16(dB + i * 16, src + i * 16, true);
    };

    stage_A(0, 0);
    stage_B(0, 0);
    cp_commit();

    for (int j = 0; j < nitems; j++) {
        int jn = j + 1;
        if (jn < nitems) {
            int an = jn / 3;
            if (jn % 3 == 0) stage_A(an & 1, an);
            stage_B(jn & 1, jn);
        }
        cp_commit();
        if (jn < nitems) cp_wait1(); else cp_wait0();
        __syncthreads();

        int q = j % 3;
        uint32_t dA = sA0 + ((j / 3) & 1) * AB;
        uint32_t dB = sB0 + (j & 1) * TB;
        uint32_t aB0 = dA + (uint32_t)(q + wM * (MI * 16) + gid) * PKB + tig * 4 + wK * CIN;
        uint32_t bB0 = dB + (uint32_t)(wN * 32 + gid) * PKB + tig * 4 + wK * CIN;
#pragma unroll
        for (int ks = 0; ks < KS; ks++) {
            uint32_t ko = ks * 32;
            uint32_t ah[MI][4], al[MI][4];
#pragma unroll
            for (int mi = 0; mi < MI; mi++) {
                uint32_t a = aB0 + mi * 16 * PKB + ko;
                ah[mi][0] = lds32(a);
                ah[mi][1] = lds32(a + 8 * PKB);
                ah[mi][2] = lds32(a + 16);
                ah[mi][3] = lds32(a + 8 * PKB + 16);
                uint32_t b = a + SA;
                al[mi][0] = lds32(b);
                al[mi][1] = lds32(b + 8 * PKB);
                al[mi][2] = lds32(b + 16);
                al[mi][3] = lds32(b + 8 * PKB + 16);
            }
#pragma unroll
            for (int nj = 0; nj < 4; nj++) {
                uint32_t bh = bB0 + nj * 8 * PKB + ko;
                uint32_t bh0 = lds32(bh);
                uint32_t bh1 = lds32(bh + 16);
                uint32_t bl0 = lds32(bh + COUT * PKB);
                uint32_t bl1 = lds32(bh + COUT * PKB + 16);
#pragma unroll
                for (int mi = 0; mi < MI; mi++) {
                    float* dd = acc[mi][nj];
                    mma_bf16(dd[0], dd[1], dd[2], dd[3],
                             ah[mi][0], ah[mi][1], ah[mi][2], ah[mi][3], bh0, bh1);
                    mma_bf16(dd[0], dd[1], dd[2], dd[3],
                             ah[mi][0], ah[mi][1], ah[mi][2], ah[mi][3], bl0, bl1);
                    mma_bf16(dd[0], dd[1], dd[2], dd[3],
                             al[mi][0], al[mi][1], al[mi][2], al[mi][3], bh0, bh1);
                }
            }
        }
        __syncthreads();
    }

    // ---- K-half reduction via smem (reuse B buffers) ----
    constexpr int FR = MI * 4;               // float4 frags per thread
    uint32_t rbase = sB0 + (uint32_t)wmn * (FR * 32 * 16);
    if (wK == 1) {
#pragma unroll
        for (int mi = 0; mi < MI; mi++)
#pragma unroll
            for (int nj = 0; nj < 4; nj++) {
                int jf = mi * 4 + nj;
                sts128f(rbase + (uint32_t)(jf * 32 + lane) * 16,
                        acc[mi][nj][0], acc[mi][nj][1], acc[mi][nj][2], acc[mi][nj][3]);
            }
    }
    __syncthreads();
    if (wK == 0) {
#pragma unroll
        for (int mi = 0; mi < MI; mi++)
#pragma unroll
            for (int nj = 0; nj < 4; nj++) {
                int jf = mi * 4 + nj;
                float t0, t1, t2, t3;
                lds128f(rbase + (uint32_t)(jf * 32 + lane) * 16, t0, t1, t2, t3);
                acc[mi][nj][0] += t0; acc[mi][nj][1] += t1;
                acc[mi][nj][2] += t2; acc[mi][nj][3] += t3;
            }

        // ---- epilogue: relu + store ----
#pragma unroll
        for (int mi = 0; mi < MI; mi++) {
            int row = wM * (MI * 16) + mi * 16 + gid;
            size_t base0 = (((size_t)od * HO + oh) * WO + ow0 + row) * COUT;
            size_t base1 = base0 + 8 * COUT;      // row + 8
#pragma unroll
            for (int nj = 0; nj < 4; nj++) {
                int col = wN * 32 + nj * 8 + tig * 2;
                float v00 = fmaxf(acc[mi][nj][0], 0.f);
                float v01 = fmaxf(acc[mi][nj][1], 0.f);
                float v10 = fmaxf(acc[mi][nj][2], 0.f);
                float v11 = fmaxf(acc[mi][nj][3], 0.f);
                if (OBF) {
                    uint32_t h0, l0, h1, l1;
                    split2(v00, v01, h0, l0);
                    split2(v10, v11, h1, l1);
                    *(uint32_t*)(out_h + base0 + col) = h0;
                    *(uint32_t*)(out_l + base0 + col) = l0;
                    *(uint32_t*)(out_h + base1 + col) = h1;
                    *(uint32_t*)(out_l + base1 + col) = l1;
                } else {
                    *(float2*)(out_f + base0 + col) = make_float2(v00, v01);
                    *(float2*)(out_f + base1 + col) = make_float2(v10, v11);
                }
            }
        }
    }
}

// ---------------- K5: conv3d 32->1 (no relu), smem-tiled ----------------
__global__ void __launch_bounds__(256)
k_reg2(const float* __restrict__ w2)
{
    __shared__ float ws_t[27 * 32];                 // [k27][ic32]
    __shared__ float tile[10][34][32];              // [zh][zw][c]
    int tx = threadIdx.x & 31;
    int ty = threadIdx.x >> 5;
    int tid = threadIdx.x;
    for (int i = tid; i < 864; i += 256) {
        int ic = i / 27, k = i % 27;
        ws_t[k * 32 + ic] = w2[i];
    }

    int ow0 = blockIdx.x * 32;
    int oh0 = blockIdx.y * 8;
    int od  = blockIdx.z;
    int ow = ow0 + tx, oh = oh0 + ty;

    float acc = 0.f;
    for (int kd = 0; kd < 3; kd++) {
        int zd = od + kd - 1;
        if (zd < 0 || zd >= DSLICE) continue;
        __syncthreads();
        for (int i = tid; i < 10 * 34 * 8; i += 256) {
            int g  = i & 7;
            int zw = (i >> 3) % 34 + ow0 - 1;
            int zh = (i >> 3) / 34 + oh0 - 1;
            bool v = (zw >= 0 && zw < WO && zh >= 0 && zh < HO);
            int zwc = v ? zw : 0, zhc = v ? zh : 0;
            const float* src = g_x2 + (((size_t)zd * HO + zhc) * WO + zwc) * C3 + g * 4;
            cp_async16(smem_u32(&tile[(i >> 3) / 34][(i >> 3) % 34][g * 4]), src, v);
        }
        cp_commit();
        cp_wait0();
        __syncthreads();

#pragma unroll
        for (int kh = 0; kh < 3; kh++) {
#pragma unroll
            for (int kw = 0; kw < 3; kw++) {
                int k = kd * 9 + kh * 3 + kw;
                const float4* p  = (const float4*)&tile[ty + kh][tx + kw][0];
                const float4* wv = (const float4*)&ws_t[k * 32];
#pragma unroll
                for (int qq = 0; qq < 8; qq++) {
                    float4 a = p[qq], b = wv[qq];
                    acc += a.x * b.x + a.y * b.y + a.z * b.z + a.w * b.w;
                }
            }
        }
    }
    g_x3[((size_t)od * HO + oh) * WO + ow] = acc;
}

// ---------------- K6: D-resize 4->8 + softmax + expectation ----------------
__global__ void k_final(float* __restrict__ outp)
{
    int pos = blockIdx.x * 256 + threadIdx.x;
    float v[4];
#pragma unroll
    for (int d = 0; d < 4; d++) v[d] = g_x3[(size_t)d * (HO * WO) + pos];

    float y[8];
#pragma unroll
    for (int o = 0; o < 8; o++) {
        float s = 0.5f * o - 0.25f;
        int j0 = max(0, (int)ceilf(s - 1.f));
        int j1 = min(3, (int)floorf(s + 1.f));
        float acc = 0.f, wsum = 0.f;
        for (int j = j0; j <= j1; j++) {
            float w = fmaxf(1.f - fabsf(s - (float)j), 0.f);
            acc += w * v[j]; wsum += w;
        }
        y[o] = acc / wsum;
    }
    float m = y[0];
#pragma unroll
    for (int o = 1; o < 8; o++) m = fmaxf(m, y[o]);
    float esum = 0.f, dsum = 0.f;
#pragma unroll
    for (int o = 0; o < 8; o++) {
        float e = expf(y[o] - m);
        esum += e;
        dsum += e * (float)o;
    }
    outp[pos] = dsum / esum;
}

// ---------------- host launch ----------------
extern "C" void kernel_launch(void* const* d_in, const int* in_sizes, int n_in,
                              void* d_out, int out_size)
{
    const float* cams[4] = { (const float*)d_in[0], (const float*)d_in[1],
                             (const float*)d_in[2], (const float*)d_in[3] };
    const float* grids    = (const float*)d_in[4];
    const float* w_feat   = (const float*)d_in[5];
    const float* w_fusion = (const float*)d_in[6];
    const float* w_reg1   = (const float*)d_in[7];
    const float* w_reg2   = (const float*)d_in[8];
    float* out = (float*)d_out;

    __nv_bfloat16 *p_wB1, *p_wB2, *p_ch, *p_cl, *p_x1h, *p_x1l;
    float* p_x2;
    cudaGetSymbolAddress((void**)&p_x2,  g_x2);
    cudaGetSymbolAddress((void**)&p_wB1, g_wB1);
    cudaGetSymbolAddress((void**)&p_wB2, g_wB2);
    cudaGetSymbolAddress((void**)&p_ch,  g_costs_h);
    cudaGetSymbolAddress((void**)&p_cl,  g_costs_l);
    cudaGetSymbolAddress((void**)&p_x1h, g_x1_h);
    cudaGetSymbolAddress((void**)&p_x1l, g_x1_l);

    const int SMEM1 = 4 * (130 * PK1 * 2) + 2 * 2 * C2 * PK1 * 2;   // 211072
    const int SMEM2 = 4 * (130 * PK2 * 2) + 2 * 2 * C3 * PK2 * 2;   //  93312
    cudaFuncSetAttribute((const void*)k_conv3d_mma<CF, C2, 4, true>,
                         cudaFuncAttributeMaxDynamicSharedMemorySize, SMEM1);
    cudaFuncSetAttribute((const void*)k_conv3d_mma<C2, C3, 2, false>,
                         cudaFuncAttributeMaxDynamicSharedMemorySize, SMEM2);

    // 1: feature extraction + weight prep (fused)
    k_feat4w<<<dim3(FW / 16, FH / 16, 5), dim3(16, 16)>>>(
        cams[0], cams[1], cams[2], cams[3], w_feat, w_fusion, w_reg1);

    // 2: plane sweep warp (2 d per thread)
    k_warp<<<dim3(FH * FW / 32, 2, CAMS), 256>>>(grids);

    // 3: antialiased resize -> bf16 hi/lo cost volume
    k_resize<<<dim3(HO * WO / 32, DSLICE, CAMS), 256>>>();

    // 4: conv1 (profiled launch)  5: conv2 — K-split mma.sync
    k_conv3d_mma<CF, C2, 4, true ><<<dim3(WO / 128, HO, DSLICE), 256, SMEM1>>>(p_ch,  p_cl,  p_wB1, p_x1h, p_x1l, nullptr);
    k_conv3d_mma<C2, C3, 2, false><<<dim3(WO / 128, HO, DSLICE), 256, SMEM2>>>(p_x1h, p_x1l, p_wB2, nullptr, nullptr, p_x2);

    // 6: squeeze conv
    k_reg2<<<dim3(WO / 32, HO / 8, DSLICE), 256>>>(w_reg2);

    // 7: disparity regression
    k_final<<<(HO * WO) / 256, 256>>>(out);
}

// round 8
// speedup vs baseline: 1.0223x; 1.0223x over previous
#include <cuda_runtime.h>
#include <cuda_bf16.h>
#include <cstdint>
#include <math.h>

// ---------------- problem constants ----------------
#define CAMS   4
#define DSLICE 4      // D = NDISP/2
#define NDISP  8
#define IH     640
#define IW     1280
#define FH     320
#define FW     640
#define C1     32
#define HO     256
#define WO     256
#define CF     128    // fused cost channels
#define C2     64
#define C3     32

#define PK1    (CF + 8)    // padded K (elements) conv1
#define PK2    (C2 + 8)    // padded K conv2

// ---------------- scratch (static device memory; no allocs) ----------------
__device__ float g_feat [(size_t)CAMS*FH*FW*C1];              // [cam][y][x][c]
__device__ float g_warp [(size_t)CAMS*DSLICE*FH*FW*C1];       // [cam][d][y][x][c]
__device__ __nv_bfloat16 g_costs_h[(size_t)DSLICE*HO*WO*CF];  // hi plane, [d][h][w][c]
__device__ __nv_bfloat16 g_costs_l[(size_t)DSLICE*HO*WO*CF];  // lo plane
__device__ __nv_bfloat16 g_x1_h  [(size_t)DSLICE*HO*WO*C2];
__device__ __nv_bfloat16 g_x1_l  [(size_t)DSLICE*HO*WO*C2];
__device__ float g_x2   [(size_t)DSLICE*HO*WO*C3];
__device__ float g_x3   [(size_t)DSLICE*HO*WO];
__device__ __nv_bfloat16 g_wB1[27*2*C2*PK1];   // [tap][hi/lo][n][PK1]
__device__ __nv_bfloat16 g_wB2[27*2*C3*PK2];   // [tap][hi/lo][n][PK2]

// =====================================================================
// helpers
// =====================================================================
__device__ __forceinline__ uint32_t smem_u32(const void* p) {
    uint32_t a;
    asm("{ .reg .u64 t; cvta.to.shared.u64 t, %1; cvt.u32.u64 %0, t; }" : "=r"(a) : "l"(p));
    return a;
}
__device__ __forceinline__ uint32_t lds32(uint32_t addr) {
    uint32_t r;
    asm volatile("ld.shared.b32 %0, [%1];" : "=r"(r) : "r"(addr));
    return r;
}
__device__ __forceinline__ void cp_async16(uint32_t dst, const void* src, bool valid) {
    int sz = valid ? 16 : 0;
    asm volatile("cp.async.cg.shared.global [%0], [%1], 16, %2;"
                 :: "r"(dst), "l"(src), "r"(sz) : "memory");
}
__device__ __forceinline__ void cp_commit() {
    asm volatile("cp.async.commit_group;" ::: "memory");
}
__device__ __forceinline__ void cp_wait1() {
    asm volatile("cp.async.wait_group 1;" ::: "memory");
}
__device__ __forceinline__ void cp_wait0() {
    asm volatile("cp.async.wait_group 0;" ::: "memory");
}
__device__ __forceinline__ void mma_bf16(float& d0, float& d1, float& d2, float& d3,
                                         uint32_t a0, uint32_t a1, uint32_t a2, uint32_t a3,
                                         uint32_t b0, uint32_t b1)
{
    asm volatile(
        "mma.sync.aligned.m16n8k16.row.col.f32.bf16.bf16.f32 "
        "{%0,%1,%2,%3}, {%4,%5,%6,%7}, {%8,%9}, {%0,%1,%2,%3};"
        : "+f"(d0), "+f"(d1), "+f"(d2), "+f"(d3)
        : "r"(a0), "r"(a1), "r"(a2), "r"(a3), "r"(b0), "r"(b1));
}
// pack two floats into bf16x2 hi pair + residual bf16x2 lo pair
__device__ __forceinline__ void split2(float x0, float x1, uint32_t& hi, uint32_t& lo)
{
    __nv_bfloat16 h0 = __float2bfloat16(x0);
    __nv_bfloat16 h1 = __float2bfloat16(x1);
    float r0 = x0 - __bfloat162float(h0);
    float r1 = x1 - __bfloat162float(h1);
    __nv_bfloat162 hp = __halves2bfloat162(h0, h1);
    __nv_bfloat162 lp = __halves2bfloat162(__float2bfloat16(r0), __float2bfloat16(r1));
    hi = *(uint32_t*)&hp;
    lo = *(uint32_t*)&lp;
}

// ---------------- K1: conv2d 3->32 s2 + relu (grid.z<4) fused with weight prep (grid.z==4) ----
__global__ void k_feat4w(const float* __restrict__ c0, const float* __restrict__ c1,
                         const float* __restrict__ c2, const float* __restrict__ c3,
                         const float* __restrict__ w,
                         const float* __restrict__ w_fusion, const float* __restrict__ w_reg1)
{
    int tid = threadIdx.y * 16 + threadIdx.x;
    int zi  = blockIdx.z;

    if (zi == 4) {
        int idx0   = (blockIdx.y * (FW / 16) + blockIdx.x) * 256 + tid;
        int stride = (FW / 16) * (FH / 16) * 256;
        for (int i = idx0; i < 27 * C2 * CF; i += stride) {
            int k = i % CF;
            int n = (i / CF) % C2;
            int t = i / (CF * C2);
            int kw = t % 3, kh = (t / 3) % 3, kd = t / 9;
            float v = w_fusion[((((size_t)n * CF + k) * 3 + kd) * 3 + kh) * 3 + kw];
            __nv_bfloat16 h = __float2bfloat16(v);
            __nv_bfloat16 l = __float2bfloat16(v - __bfloat162float(h));
            g_wB1[((size_t)(t * 2 + 0) * C2 + n) * PK1 + k] = h;
            g_wB1[((size_t)(t * 2 + 1) * C2 + n) * PK1 + k] = l;
        }
        for (int i = idx0; i < 27 * C3 * C2; i += stride) {
            int k = i % C2;
            int n = (i / C2) % C3;
            int t = i / (C2 * C3);
            int kw = t % 3, kh = (t / 3) % 3, kd = t / 9;
            float v = w_reg1[((((size_t)n * C2 + k) * 3 + kd) * 3 + kh) * 3 + kw];
            __nv_bfloat16 h = __float2bfloat16(v);
            __nv_bfloat16 l = __float2bfloat16(v - __bfloat162float(h));
            g_wB2[((size_t)(t * 2 + 0) * C3 + n) * PK2 + k] = h;
            g_wB2[((size_t)(t * 2 + 1) * C3 + n) * PK2 + k] = l;
        }
        return;
    }

    __shared__ float ws[27 * 32];
    for (int i = tid; i < 864; i += 256) {
        int k = i >> 5, oc = i & 31;
        ws[i] = w[oc * 27 + k];
    }
    __syncthreads();

    const float* cam = (zi == 0) ? c0 : (zi == 1) ? c1 : (zi == 2) ? c2 : c3;
    int ow = blockIdx.x * 16 + threadIdx.x;
    int oh = blockIdx.y * 16 + threadIdx.y;

    float v[27];
#pragma unroll
    for (int ic = 0; ic < 3; ic++)
#pragma unroll
        for (int kh = 0; kh < 3; kh++)
#pragma unroll
            for (int kw = 0; kw < 3; kw++) {
                int iy = 2 * oh + kh - 1;
                int ix = 2 * ow + kw - 1;
                float t = 0.f;
                if (iy >= 0 && iy < IH && ix >= 0 && ix < IW)
                    t = cam[(size_t)ic * IH * IW + (size_t)iy * IW + ix];
                v[ic * 9 + kh * 3 + kw] = t;
            }

    float4 acc[8];
#pragma unroll
    for (int q = 0; q < 8; q++) acc[q] = make_float4(0.f, 0.f, 0.f, 0.f);
    const float4* ws4 = (const float4*)ws;
#pragma unroll
    for (int k = 0; k < 27; k++) {
        float vv = v[k];
#pragma unroll
        for (int q = 0; q < 8; q++) {
            float4 wv = ws4[k * 8 + q];
            acc[q].x += vv * wv.x;  acc[q].y += vv * wv.y;
            acc[q].z += vv * wv.z;  acc[q].w += vv * wv.w;
        }
    }
    float4* o = (float4*)(g_feat + ((size_t)zi * FH * FW + (size_t)oh * FW + ow) * C1);
#pragma unroll
    for (int q = 0; q < 8; q++) {
        float4 r = acc[q];
        r.x = fmaxf(r.x, 0.f); r.y = fmaxf(r.y, 0.f);
        r.z = fmaxf(r.z, 0.f); r.w = fmaxf(r.w, 0.f);
        o[q] = r;
    }
}

// ---------------- K2: grid_sample, warp-cooperative, 2 d-slices per thread ----------------
__global__ void __launch_bounds__(256)
k_warp(const float* __restrict__ grids)
{
    int tid = threadIdx.x;
    int c   = tid & 7;
    int pid = tid >> 3;
    int pos = blockIdx.x * 32 + pid;
    int d0  = blockIdx.y;
    int cam = blockIdx.z;
    int y = pos / FW, x = pos % FW;

    const float* fb = g_feat + (size_t)cam * FH * FW * C1 + c * 4;

#pragma unroll
    for (int s = 0; s < 2; s++) {
        int d = d0 + s * 2;
        const float* g = grids + ((((size_t)cam * DSLICE + d) * FH + y) * FW + x) * 2;
        float fx = (g[0] + 1.f) * (FW * 0.5f) - 0.5f;
        float fy = (g[1] + 1.f) * (FH * 0.5f) - 0.5f;
        float x0f = floorf(fx), y0f = floorf(fy);
        float wx = fx - x0f,   wy = fy - y0f;
        int x0 = (int)x0f, y0 = (int)y0f;
        int x1 = x0 + 1,   y1 = y0 + 1;
        float vx0 = (x0 >= 0 && x0 < FW) ? 1.f : 0.f;
        float vx1 = (x1 >= 0 && x1 < FW) ? 1.f : 0.f;
        float vy0 = (y0 >= 0 && y0 < FH) ? 1.f : 0.f;
        float vy1 = (y1 >= 0 && y1 < FH) ? 1.f : 0.f;
        float w00 = (1.f - wx) * (1.f - wy) * vx0 * vy0;
        float w01 = wx * (1.f - wy) * vx1 * vy0;
        float w10 = (1.f - wx) * wy * vx0 * vy1;
        float w11 = wx * wy * vx1 * vy1;
        int x0c = min(max(x0, 0), FW - 1), x1c = min(max(x1, 0), FW - 1);
        int y0c = min(max(y0, 0), FH - 1), y1c = min(max(y1, 0), FH - 1);

        float4 a = *(const float4*)(fb + ((size_t)y0c * FW + x0c) * C1);
        float4 b = *(const float4*)(fb + ((size_t)y0c * FW + x1c) * C1);
        float4 e = *(const float4*)(fb + ((size_t)y1c * FW + x0c) * C1);
        float4 f = *(const float4*)(fb + ((size_t)y1c * FW + x1c) * C1);

        float4 r;
        r.x = w00 * a.x + w01 * b.x + w10 * e.x + w11 * f.x;
        r.y = w00 * a.y + w01 * b.y + w10 * e.y + w11 * f.y;
        r.z = w00 * a.z + w01 * b.z + w10 * e.z + w11 * f.z;
        r.w = w00 * a.w + w01 * b.w + w10 * e.w + w11 * f.w;
        *(float4*)(g_warp + ((size_t)(cam * DSLICE + d) * FH * FW + pos) * C1 + c * 4) = r;
    }
}

// ---------------- K3: antialiased resize, warp-cooperative, bf16 hi/lo output ----------------
__global__ void __launch_bounds__(256)
k_resize()
{
    int tid  = threadIdx.x;
    int c    = tid & 7;
    int pid  = tid >> 3;
    int opos = blockIdx.x * 32 + pid;
    int ho   = opos >> 8;
    int wo   = opos & 255;
    int d    = blockIdx.y;
    int cam  = blockIdx.z;

    float sy = (ho + 0.5f) * 1.25f - 0.5f;
    int jy0 = max((int)ceilf(sy - 1.25f), 0);
    int jy1 = min((int)floorf(sy + 1.25f), FH - 1);
    float wyv[4]; int ny = jy1 - jy0 + 1;
    float sumy = 0.f;
    for (int i = 0; i < ny; i++) {
        float w = fmaxf(1.f - fabsf(sy - (float)(jy0 + i)) * 0.8f, 0.f);
        wyv[i] = w; sumy += w;
    }
    for (int i = 0; i < ny; i++) wyv[i] /= sumy;

    float sx = (wo + 0.5f) * 2.5f - 0.5f;
    int jx0 = max((int)ceilf(sx - 2.5f), 0);
    int jx1 = min((int)floorf(sx + 2.5f), FW - 1);
    float wxv[6]; int nx = jx1 - jx0 + 1;
    float sumx = 0.f;
    for (int i = 0; i < nx; i++) {
        float w = fmaxf(1.f - fabsf(sx - (float)(jx0 + i)) * 0.4f, 0.f);
        wxv[i] = w; sumx += w;
    }
    for (int i = 0; i < nx; i++) wxv[i] /= sumx;

    float4 acc = make_float4(0.f, 0.f, 0.f, 0.f);
    const float* base = g_warp + (size_t)(cam * DSLICE + d) * FH * FW * C1 + c * 4;
    for (int iy = 0; iy < ny; iy++) {
        const float* rowb = base + (size_t)(jy0 + iy) * FW * C1;
        for (int ix = 0; ix < nx; ix++) {
            float wgt = wyv[iy] * wxv[ix];
            float4 t = *(const float4*)(rowb + (size_t)(jx0 + ix) * C1);
            acc.x += wgt * t.x; acc.y += wgt * t.y;
            acc.z += wgt * t.z; acc.w += wgt * t.w;
        }
    }
    size_t obase = (((size_t)d * HO + ho) * WO + wo) * CF + cam * C1 + c * 4;
    uint32_t h0, l0, h1, l1;
    split2(acc.x, acc.y, h0, l0);
    split2(acc.z, acc.w, h1, l1);
    *(uint2*)(g_costs_h + obase) = make_uint2(h0, h1);
    *(uint2*)(g_costs_l + obase) = make_uint2(l0, l1);
}

// ---------------- K4: conv3d 3x3x3 pad1 + relu, mma.sync bf16 split, reg-pipelined ----------
// 128 threads / 4 warps. Warp tile (MI*16) x 32 from block M128 x N(32*NWN).
// conv1: MI=4, NWN=2 (warp M64xN32). conv2: MI=2, NWN=1 (warp M32xN32).
// Inner loop: register double-buffered smem fragments; split-outermost mma order.
template<int CIN, int COUT, int MI, int NWN, bool OBF>
__global__ void __launch_bounds__(128)
k_conv3d_mma(const __nv_bfloat16* __restrict__ in_h, const __nv_bfloat16* __restrict__ in_l,
             const __nv_bfloat16* __restrict__ wB,
             __nv_bfloat16* __restrict__ out_h, __nv_bfloat16* __restrict__ out_l,
             float* __restrict__ out_f)
{
    constexpr int NT   = 128;
    constexpr int PK   = CIN + 8;
    constexpr int PKB  = PK * 2;             // bytes per smem row
    constexpr int SA   = 130 * PKB;          // one A plane (hi or lo)
    constexpr int AB   = 2 * SA;             // A buffer (hi + lo)
    constexpr int TB   = 2 * COUT * PKB;     // one B tap (hi + lo)
    constexpr int NJ   = (COUT / NWN) / 8;   // 4
    constexpr int KST  = CIN / 16;           // k-steps per item
    constexpr int CH   = CIN / 8;            // 16B chunks per A row per plane

    extern __shared__ char dsm[];
    const uint32_t sBase = smem_u32(dsm);
    const uint32_t sA0 = sBase;              // [A0 | A1 | B0 | B1]
    const uint32_t sB0 = sBase + 2 * AB;

    int tid  = threadIdx.x;
    int wid  = tid >> 5, lane = tid & 31;
    int gid  = lane >> 2, tig = lane & 3;
    int wM   = wid / NWN;
    int wN   = wid % NWN;
    int ow0  = blockIdx.x * 128;
    int oh   = blockIdx.y, od = blockIdx.z;

    // ---- build valid (kd,kh) list ----
    int zdv[9], zhv[9], t9v[9];
    int nv = 0;
    for (int kd = 0; kd < 3; kd++) {
        int zd = od + kd - 1;
        if (zd < 0 || zd >= DSLICE) continue;
        for (int kh = 0; kh < 3; kh++) {
            int zh = oh + kh - 1;
            if (zh < 0 || zh >= HO) continue;
            zdv[nv] = zd; zhv[nv] = zh; t9v[nv] = kd * 3 + kh;
            nv++;
        }
    }
    int nitems = nv * 3;

    float acc[MI][NJ][4];
#pragma unroll
    for (int mi = 0; mi < MI; mi++)
#pragma unroll
        for (int nj = 0; nj < NJ; nj++)
#pragma unroll
            for (int cc = 0; cc < 4; cc++) acc[mi][nj][cc] = 0.f;

    auto stage_A = [&](int slot, int ai) {
        size_t inoff = ((size_t)zdv[ai] * HO + zhv[ai]) * WO * CIN;
        uint32_t dA = sA0 + slot * AB;
        for (int i = tid; i < 130 * CH; i += NT) {
            int r = i / CH, g = i % CH;
            int p = ow0 - 1 + r;
            bool v = (p >= 0 && p < WO);
            int pc = v ? p : 0;
            size_t so = inoff + (size_t)pc * CIN + g * 8;
            uint32_t doff = (uint32_t)r * PKB + g * 16;
            cp_async16(dA + doff,      in_h + so, v);
            cp_async16(dA + SA + doff, in_l + so, v);
        }
    };
    auto stage_B = [&](int slot, int j) {
        int t = t9v[j / 3] * 3 + (j % 3);
        const char* src = (const char*)(wB + (size_t)t * COUT * PK * 2);
        uint32_t dB = sB0 + slot * TB;
        for (int i = tid; i < TB / 16; i += NT)
            cp_async16(dB + i * 16, src + i * 16, true);
    };

    stage_A(0, 0);
    stage_B(0, 0);
    cp_commit();

    for (int j = 0; j < nitems; j++) {
        int jn = j + 1;
        if (jn < nitems) {
            int an = jn / 3;
            if (jn % 3 == 0) stage_A(an & 1, an);
            stage_B(jn & 1, jn);
        }
        cp_commit();
        if (jn < nitems) cp_wait1(); else cp_wait0();
        __syncthreads();

        int q = j % 3;
        uint32_t dA = sA0 + ((j / 3) & 1) * AB;
        uint32_t dB = sB0 + (j & 1) * TB;
        uint32_t aB0 = dA + (uint32_t)(q + wM * (MI * 16) + gid) * PKB + tig * 4;
        uint32_t bB0 = dB + (uint32_t)(wN * 32 + gid) * PKB + tig * 4;

        // register double-buffered fragments
        uint32_t ah[2][MI][4], al[2][MI][4];
        uint32_t bh[2][NJ][2], bl[2][NJ][2];

        auto load_frags = [&](int buf, int ks) {
            uint32_t ko = (uint32_t)ks * 32;
#pragma unroll
            for (int mi = 0; mi < MI; mi++) {
                uint32_t a = aB0 + mi * 16 * PKB + ko;
                ah[buf][mi][0] = lds32(a);
                ah[buf][mi][1] = lds32(a + 8 * PKB);
                ah[buf][mi][2] = lds32(a + 16);
                ah[buf][mi][3] = lds32(a + 8 * PKB + 16);
                uint32_t b = a + SA;
                al[buf][mi][0] = lds32(b);
                al[buf][mi][1] = lds32(b + 8 * PKB);
                al[buf][mi][2] = lds32(b + 16);
                al[buf][mi][3] = lds32(b + 8 * PKB + 16);
            }
#pragma unroll
            for (int nj = 0; nj < NJ; nj++) {
                uint32_t bb = bB0 + nj * 8 * PKB + ko;
                bh[buf][nj][0] = lds32(bb);
                bh[buf][nj][1] = lds32(bb + 16);
                bl[buf][nj][0] = lds32(bb + COUT * PKB);
                bl[buf][nj][1] = lds32(bb + COUT * PKB + 16);
            }
        };

        load_frags(0, 0);
#pragma unroll
        for (int ks = 0; ks < KST; ks++) {
            int cur = ks & 1;
            if (ks + 1 < KST) load_frags(cur ^ 1, ks + 1);
            // split-outermost: consecutive mmas hit different accumulators
#pragma unroll
            for (int nj = 0; nj < NJ; nj++)
#pragma unroll
                for (int mi = 0; mi < MI; mi++)
                    mma_bf16(acc[mi][nj][0], acc[mi][nj][1], acc[mi][nj][2], acc[mi][nj][3],
                             ah[cur][mi][0], ah[cur][mi][1], ah[cur][mi][2], ah[cur][mi][3],
                             bh[cur][nj][0], bh[cur][nj][1]);
#pragma unroll
            for (int nj = 0; nj < NJ; nj++)
#pragma unroll
                for (int mi = 0; mi < MI; mi++)
                    mma_bf16(acc[mi][nj][0], acc[mi][nj][1], acc[mi][nj][2], acc[mi][nj][3],
                             ah[cur][mi][0], ah[cur][mi][1], ah[cur][mi][2], ah[cur][mi][3],
                             bl[cur][nj][0], bl[cur][nj][1]);
#pragma unroll
            for (int nj = 0; nj < NJ; nj++)
#pragma unroll
                for (int mi = 0; mi < MI; mi++)
                    mma_bf16(acc[mi][nj][0], acc[mi][nj][1], acc[mi][nj][2], acc[mi][nj][3],
                             al[cur][mi][0], al[cur][mi][1], al[cur][mi][2], al[cur][mi][3],
                             bh[cur][nj][0], bh[cur][nj][1]);
        }
        __syncthreads();
    }

    // ---- epilogue: relu + store ----
#pragma unroll
    for (int mi = 0; mi < MI; mi++) {
        int row = wM * (MI * 16) + mi * 16 + gid;
        size_t base0 = (((size_t)od * HO + oh) * WO + ow0 + row) * COUT;
        size_t base1 = base0 + 8 * COUT;      // row + 8
#pragma unroll
        for (int nj = 0; nj < NJ; nj++) {
            int col = wN * 32 + nj * 8 + tig * 2;
            float v00 = fmaxf(acc[mi][nj][0], 0.f);
            float v01 = fmaxf(acc[mi][nj][1], 0.f);
            float v10 = fmaxf(acc[mi][nj][2], 0.f);
            float v11 = fmaxf(acc[mi][nj][3], 0.f);
            if (OBF) {
                uint32_t h0, l0, h1, l1;
                split2(v00, v01, h0, l0);
                split2(v10, v11, h1, l1);
                *(uint32_t*)(out_h + base0 + col) = h0;
                *(uint32_t*)(out_l + base0 + col) = l0;
                *(uint32_t*)(out_h + base1 + col) = h1;
                *(uint32_t*)(out_l + base1 + col) = l1;
            } else {
                *(float2*)(out_f + base0 + col) = make_float2(v00, v01);
                *(float2*)(out_f + base1 + col) = make_float2(v10, v11);
            }
        }
    }
}

// ---------------- K5: conv3d 32->1 (no relu), smem-tiled ----------------
__global__ void __launch_bounds__(256)
k_reg2(const float* __restrict__ w2)
{
    __shared__ float ws_t[27 * 32];                 // [k27][ic32]
    __shared__ float tile[10][34][32];              // [zh][zw][c]
    int tx = threadIdx.x & 31;
    int ty = threadIdx.x >> 5;
    int tid = threadIdx.x;
    for (int i = tid; i < 864; i += 256) {
        int ic = i / 27, k = i % 27;
        ws_t[k * 32 + ic] = w2[i];
    }

    int ow0 = blockIdx.x * 32;
    int oh0 = blockIdx.y * 8;
    int od  = blockIdx.z;
    int ow = ow0 + tx, oh = oh0 + ty;

    float acc = 0.f;
    for (int kd = 0; kd < 3; kd++) {
        int zd = od + kd - 1;
        if (zd < 0 || zd >= DSLICE) continue;
        __syncthreads();
        for (int i = tid; i < 10 * 34 * 8; i += 256) {
            int g  = i & 7;
            int zw = (i >> 3) % 34 + ow0 - 1;
            int zh = (i >> 3) / 34 + oh0 - 1;
            bool v = (zw >= 0 && zw < WO && zh >= 0 && zh < HO);
            int zwc = v ? zw : 0, zhc = v ? zh : 0;
            const float* src = g_x2 + (((size_t)zd * HO + zhc) * WO + zwc) * C3 + g * 4;
            cp_async16(smem_u32(&tile[(i >> 3) / 34][(i >> 3) % 34][g * 4]), src, v);
        }
        cp_commit();
        cp_wait0();
        __syncthreads();

#pragma unroll
        for (int kh = 0; kh < 3; kh++) {
#pragma unroll
            for (int kw = 0; kw < 3; kw++) {
                int k = kd * 9 + kh * 3 + kw;
                const float4* p  = (const float4*)&tile[ty + kh][tx + kw][0];
                const float4* wv = (const float4*)&ws_t[k * 32];
#pragma unroll
                for (int qq = 0; qq < 8; qq++) {
                    float4 a = p[qq], b = wv[qq];
                    acc += a.x * b.x + a.y * b.y + a.z * b.z + a.w * b.w;
                }
            }
        }
    }
    g_x3[((size_t)od * HO + oh) * WO + ow] = acc;
}

// ---------------- K6: D-resize 4->8 + softmax + expectation ----------------
__global__ void k_final(float* __restrict__ outp)
{
    int pos = blockIdx.x * 256 + threadIdx.x;
    float v[4];
#pragma unroll
    for (int d = 0; d < 4; d++) v[d] = g_x3[(size_t)d * (HO * WO) + pos];

    float y[8];
#pragma unroll
    for (int o = 0; o < 8; o++) {
        float s = 0.5f * o - 0.25f;
        int j0 = max(0, (int)ceilf(s - 1.f));
        int j1 = min(3, (int)floorf(s + 1.f));
        float acc = 0.f, wsum = 0.f;
        for (int j = j0; j <= j1; j++) {
            float w = fmaxf(1.f - fabsf(s - (float)j), 0.f);
            acc += w * v[j]; wsum += w;
        }
        y[o] = acc / wsum;
    }
    float m = y[0];
#pragma unroll
    for (int o = 1; o < 8; o++) m = fmaxf(m, y[o]);
    float esum = 0.f, dsum = 0.f;
#pragma unroll
    for (int o = 0; o < 8; o++) {
        float e = expf(y[o] - m);
        esum += e;
        dsum += e * (float)o;
    }
    outp[pos] = dsum / esum;
}

// ---------------- host launch ----------------
extern "C" void kernel_launch(void* const* d_in, const int* in_sizes, int n_in,
                              void* d_out, int out_size)
{
    const float* cams[4] = { (const float*)d_in[0], (const float*)d_in[1],
                             (const float*)d_in[2], (const float*)d_in[3] };
    const float* grids    = (const float*)d_in[4];
    const float* w_feat   = (const float*)d_in[5];
    const float* w_fusion = (const float*)d_in[6];
    const float* w_reg1   = (const float*)d_in[7];
    const float* w_reg2   = (const float*)d_in[8];
    float* out = (float*)d_out;

    __nv_bfloat16 *p_wB1, *p_wB2, *p_ch, *p_cl, *p_x1h, *p_x1l;
    float* p_x2;
    cudaGetSymbolAddress((void**)&p_x2,  g_x2);
    cudaGetSymbolAddress((void**)&p_wB1, g_wB1);
    cudaGetSymbolAddress((void**)&p_wB2, g_wB2);
    cudaGetSymbolAddress((void**)&p_ch,  g_costs_h);
    cudaGetSymbolAddress((void**)&p_cl,  g_costs_l);
    cudaGetSymbolAddress((void**)&p_x1h, g_x1_h);
    cudaGetSymbolAddress((void**)&p_x1l, g_x1_l);

    const int SMEM1 = 4 * (130 * PK1 * 2) + 2 * 2 * C2 * PK1 * 2;   // 211072
    const int SMEM2 = 4 * (130 * PK2 * 2) + 2 * 2 * C3 * PK2 * 2;   //  93312
    cudaFuncSetAttribute((const void*)k_conv3d_mma<CF, C2, 4, 2, true>,
                         cudaFuncAttributeMaxDynamicSharedMemorySize, SMEM1);
    cudaFuncSetAttribute((const void*)k_conv3d_mma<C2, C3, 2, 1, false>,
                         cudaFuncAttributeMaxDynamicSharedMemorySize, SMEM2);

    // 1: feature extraction + weight prep (fused)
    k_feat4w<<<dim3(FW / 16, FH / 16, 5), dim3(16, 16)>>>(
        cams[0], cams[1], cams[2], cams[3], w_feat, w_fusion, w_reg1);

    // 2: plane sweep warp (2 d per thread)
    k_warp<<<dim3(FH * FW / 32, 2, CAMS), 256>>>(grids);

    // 3: antialiased resize -> bf16 hi/lo cost volume
    k_resize<<<dim3(HO * WO / 32, DSLICE, CAMS), 256>>>();

    // 4: conv1 (profiled launch)  5: conv2 — reg-pipelined mma.sync
    k_conv3d_mma<CF, C2, 4, 2, true ><<<dim3(WO / 128, HO, DSLICE), 128, SMEM1>>>(p_ch,  p_cl,  p_wB1, p_x1h, p_x1l, nullptr);
    k_conv3d_mma<C2, C3, 2, 1, false><<<dim3(WO / 128, HO, DSLICE), 128, SMEM2>>>(p_x1h, p_x1l, p_wB2, nullptr, nullptr, p_x2);

    // 6: squeeze conv
    k_reg2<<<dim3(WO / 32, HO / 8, DSLICE), 256>>>(w_reg2);

    // 7: disparity regression
    k_final<<<(HO * WO) / 256, 256>>>(out);
}

// round 9
// speedup vs baseline: 1.0899x; 1.0661x over previous
#include <cuda_runtime.h>
#include <cuda_bf16.h>
#include <cstdint>
#include <math.h>

// ---------------- problem constants ----------------
#define CAMS   4
#define DSLICE 4      // D = NDISP/2
#define NDISP  8
#define IH     640
#define IW     1280
#define FH     320
#define FW     640
#define C1     32
#define HO     256
#define WO     256
#define CF     128    // fused cost channels
#define C2     64
#define C3     32

#define PK1    (CF + 8)    // padded K (elements) conv1
#define PK2    (C2 + 8)    // padded K conv2

// ---------------- scratch (static device memory; no allocs) ----------------
__device__ float g_feat [(size_t)CAMS*FH*FW*C1];              // [cam][y][x][c]
__device__ float g_warp [(size_t)CAMS*DSLICE*FH*FW*C1];       // [cam][d][y][x][c]
__device__ __nv_bfloat16 g_costs_h[(size_t)DSLICE*HO*WO*CF];  // hi plane, [d][h][w][c]
__device__ __nv_bfloat16 g_costs_l[(size_t)DSLICE*HO*WO*CF];  // lo plane
__device__ __nv_bfloat16 g_x1_h  [(size_t)DSLICE*HO*WO*C2];
__device__ __nv_bfloat16 g_x1_l  [(size_t)DSLICE*HO*WO*C2];
__device__ float g_x2   [(size_t)DSLICE*HO*WO*C3];
__device__ float g_x3   [(size_t)DSLICE*HO*WO];
__device__ __nv_bfloat16 g_wB1[27*2*C2*PK1];   // [tap][hi/lo][n][PK1]
__device__ __nv_bfloat16 g_wB2[27*2*C3*PK2];   // [tap][hi/lo][n][PK2]

// =====================================================================
// helpers
// =====================================================================
__device__ __forceinline__ uint32_t smem_u32(const void* p) {
    uint32_t a;
    asm("{ .reg .u64 t; cvta.to.shared.u64 t, %1; cvt.u32.u64 %0, t; }" : "=r"(a) : "l"(p));
    return a;
}
__device__ __forceinline__ uint32_t lds32(uint32_t addr) {
    uint32_t r;
    asm volatile("ld.shared.b32 %0, [%1];" : "=r"(r) : "r"(addr));
    return r;
}
__device__ __forceinline__ void cp_async16(uint32_t dst, const void* src, bool valid) {
    int sz = valid ? 16 : 0;
    asm volatile("cp.async.cg.shared.global [%0], [%1], 16, %2;"
                 :: "r"(dst), "l"(src), "r"(sz) : "memory");
}
__device__ __forceinline__ void cp_commit() {
    asm volatile("cp.async.commit_group;" ::: "memory");
}
__device__ __forceinline__ void cp_wait0() {
    asm volatile("cp.async.wait_group 0;" ::: "memory");
}
__device__ __forceinline__ void mma_bf16(float& d0, float& d1, float& d2, float& d3,
                                         uint32_t a0, uint32_t a1, uint32_t a2, uint32_t a3,
                                         uint32_t b0, uint32_t b1)
{
    asm volatile(
        "mma.sync.aligned.m16n8k16.row.col.f32.bf16.bf16.f32 "
        "{%0,%1,%2,%3}, {%4,%5,%6,%7}, {%8,%9}, {%0,%1,%2,%3};"
        : "+f"(d0), "+f"(d1), "+f"(d2), "+f"(d3)
        : "r"(a0), "r"(a1), "r"(a2), "r"(a3), "r"(b0), "r"(b1));
}
// pack two floats into bf16x2 hi pair + residual bf16x2 lo pair
__device__ __forceinline__ void split2(float x0, float x1, uint32_t& hi, uint32_t& lo)
{
    __nv_bfloat16 h0 = __float2bfloat16(x0);
    __nv_bfloat16 h1 = __float2bfloat16(x1);
    float r0 = x0 - __bfloat162float(h0);
    float r1 = x1 - __bfloat162float(h1);
    __nv_bfloat162 hp = __halves2bfloat162(h0, h1);
    __nv_bfloat162 lp = __halves2bfloat162(__float2bfloat16(r0), __float2bfloat16(r1));
    hi = *(uint32_t*)&hp;
    lo = *(uint32_t*)&lp;
}

// ---------------- K1: conv2d 3->32 s2 + relu (grid.z<4) fused with weight prep (grid.z==4) ----
__global__ void k_feat4w(const float* __restrict__ c0, const float* __restrict__ c1,
                         const float* __restrict__ c2, const float* __restrict__ c3,
                         const float* __restrict__ w,
                         const float* __restrict__ w_fusion, const float* __restrict__ w_reg1)
{
    int tid = threadIdx.y * 16 + threadIdx.x;
    int zi  = blockIdx.z;

    if (zi == 4) {
        int idx0   = (blockIdx.y * (FW / 16) + blockIdx.x) * 256 + tid;
        int stride = (FW / 16) * (FH / 16) * 256;
        for (int i = idx0; i < 27 * C2 * CF; i += stride) {
            int k = i % CF;
            int n = (i / CF) % C2;
            int t = i / (CF * C2);
            int kw = t % 3, kh = (t / 3) % 3, kd = t / 9;
            float v = w_fusion[((((size_t)n * CF + k) * 3 + kd) * 3 + kh) * 3 + kw];
            __nv_bfloat16 h = __float2bfloat16(v);
            __nv_bfloat16 l = __float2bfloat16(v - __bfloat162float(h));
            g_wB1[((size_t)(t * 2 + 0) * C2 + n) * PK1 + k] = h;
            g_wB1[((size_t)(t * 2 + 1) * C2 + n) * PK1 + k] = l;
        }
        for (int i = idx0; i < 27 * C3 * C2; i += stride) {
            int k = i % C2;
            int n = (i / C2) % C3;
            int t = i / (C2 * C3);
            int kw = t % 3, kh = (t / 3) % 3, kd = t / 9;
            float v = w_reg1[((((size_t)n * C2 + k) * 3 + kd) * 3 + kh) * 3 + kw];
            __nv_bfloat16 h = __float2bfloat16(v);
            __nv_bfloat16 l = __float2bfloat16(v - __bfloat162float(h));
            g_wB2[((size_t)(t * 2 + 0) * C3 + n) * PK2 + k] = h;
            g_wB2[((size_t)(t * 2 + 1) * C3 + n) * PK2 + k] = l;
        }
        return;
    }

    __shared__ float ws[27 * 32];
    for (int i = tid; i < 864; i += 256) {
        int k = i >> 5, oc = i & 31;
        ws[i] = w[oc * 27 + k];
    }
    __syncthreads();

    const float* cam = (zi == 0) ? c0 : (zi == 1) ? c1 : (zi == 2) ? c2 : c3;
    int ow = blockIdx.x * 16 + threadIdx.x;
    int oh = blockIdx.y * 16 + threadIdx.y;

    float v[27];
#pragma unroll
    for (int ic = 0; ic < 3; ic++)
#pragma unroll
        for (int kh = 0; kh < 3; kh++)
#pragma unroll
            for (int kw = 0; kw < 3; kw++) {
                int iy = 2 * oh + kh - 1;
                int ix = 2 * ow + kw - 1;
                float t = 0.f;
                if (iy >= 0 && iy < IH && ix >= 0 && ix < IW)
                    t = cam[(size_t)ic * IH * IW + (size_t)iy * IW + ix];
                v[ic * 9 + kh * 3 + kw] = t;
            }

    float4 acc[8];
#pragma unroll
    for (int q = 0; q < 8; q++) acc[q] = make_float4(0.f, 0.f, 0.f, 0.f);
    const float4* ws4 = (const float4*)ws;
#pragma unroll
    for (int k = 0; k < 27; k++) {
        float vv = v[k];
#pragma unroll
        for (int q = 0; q < 8; q++) {
            float4 wv = ws4[k * 8 + q];
            acc[q].x += vv * wv.x;  acc[q].y += vv * wv.y;
            acc[q].z += vv * wv.z;  acc[q].w += vv * wv.w;
        }
    }
    float4* o = (float4*)(g_feat + ((size_t)zi * FH * FW + (size_t)oh * FW + ow) * C1);
#pragma unroll
    for (int q = 0; q < 8; q++) {
        float4 r = acc[q];
        r.x = fmaxf(r.x, 0.f); r.y = fmaxf(r.y, 0.f);
        r.z = fmaxf(r.z, 0.f); r.w = fmaxf(r.w, 0.f);
        o[q] = r;
    }
}

// ---------------- K2: grid_sample, warp-cooperative, 2 d-slices per thread ----------------
__global__ void __launch_bounds__(256)
k_warp(const float* __restrict__ grids)
{
    int tid = threadIdx.x;
    int c   = tid & 7;
    int pid = tid >> 3;
    int pos = blockIdx.x * 32 + pid;
    int d0  = blockIdx.y;
    int cam = blockIdx.z;
    int y = pos / FW, x = pos % FW;

    const float* fb = g_feat + (size_t)cam * FH * FW * C1 + c * 4;

#pragma unroll
    for (int s = 0; s < 2; s++) {
        int d = d0 + s * 2;
        const float* g = grids + ((((size_t)cam * DSLICE + d) * FH + y) * FW + x) * 2;
        float fx = (g[0] + 1.f) * (FW * 0.5f) - 0.5f;
        float fy = (g[1] + 1.f) * (FH * 0.5f) - 0.5f;
        float x0f = floorf(fx), y0f = floorf(fy);
        float wx = fx - x0f,   wy = fy - y0f;
        int x0 = (int)x0f, y0 = (int)y0f;
        int x1 = x0 + 1,   y1 = y0 + 1;
        float vx0 = (x0 >= 0 && x0 < FW) ? 1.f : 0.f;
        float vx1 = (x1 >= 0 && x1 < FW) ? 1.f : 0.f;
        float vy0 = (y0 >= 0 && y0 < FH) ? 1.f : 0.f;
        float vy1 = (y1 >= 0 && y1 < FH) ? 1.f : 0.f;
        float w00 = (1.f - wx) * (1.f - wy) * vx0 * vy0;
        float w01 = wx * (1.f - wy) * vx1 * vy0;
        float w10 = (1.f - wx) * wy * vx0 * vy1;
        float w11 = wx * wy * vx1 * vy1;
        int x0c = min(max(x0, 0), FW - 1), x1c = min(max(x1, 0), FW - 1);
        int y0c = min(max(y0, 0), FH - 1), y1c = min(max(y1, 0), FH - 1);

        float4 a = *(const float4*)(fb + ((size_t)y0c * FW + x0c) * C1);
        float4 b = *(const float4*)(fb + ((size_t)y0c * FW + x1c) * C1);
        float4 e = *(const float4*)(fb + ((size_t)y1c * FW + x0c) * C1);
        float4 f = *(const float4*)(fb + ((size_t)y1c * FW + x1c) * C1);

        float4 r;
        r.x = w00 * a.x + w01 * b.x + w10 * e.x + w11 * f.x;
        r.y = w00 * a.y + w01 * b.y + w10 * e.y + w11 * f.y;
        r.z = w00 * a.z + w01 * b.z + w10 * e.z + w11 * f.z;
        r.w = w00 * a.w + w01 * b.w + w10 * e.w + w11 * f.w;
        *(float4*)(g_warp + ((size_t)(cam * DSLICE + d) * FH * FW + pos) * C1 + c * 4) = r;
    }
}

// ---------------- K3: antialiased resize, warp-cooperative, bf16 hi/lo output ----------------
__global__ void __launch_bounds__(256)
k_resize()
{
    int tid  = threadIdx.x;
    int c    = tid & 7;
    int pid  = tid >> 3;
    int opos = blockIdx.x * 32 + pid;
    int ho   = opos >> 8;
    int wo   = opos & 255;
    int d    = blockIdx.y;
    int cam  = blockIdx.z;

    float sy = (ho + 0.5f) * 1.25f - 0.5f;
    int jy0 = max((int)ceilf(sy - 1.25f), 0);
    int jy1 = min((int)floorf(sy + 1.25f), FH - 1);
    float wyv[4]; int ny = jy1 - jy0 + 1;
    float sumy = 0.f;
    for (int i = 0; i < ny; i++) {
        float w = fmaxf(1.f - fabsf(sy - (float)(jy0 + i)) * 0.8f, 0.f);
        wyv[i] = w; sumy += w;
    }
    for (int i = 0; i < ny; i++) wyv[i] /= sumy;

    float sx = (wo + 0.5f) * 2.5f - 0.5f;
    int jx0 = max((int)ceilf(sx - 2.5f), 0);
    int jx1 = min((int)floorf(sx + 2.5f), FW - 1);
    float wxv[6]; int nx = jx1 - jx0 + 1;
    float sumx = 0.f;
    for (int i = 0; i < nx; i++) {
        float w = fmaxf(1.f - fabsf(sx - (float)(jx0 + i)) * 0.4f, 0.f);
        wxv[i] = w; sumx += w;
    }
    for (int i = 0; i < nx; i++) wxv[i] /= sumx;

    float4 acc = make_float4(0.f, 0.f, 0.f, 0.f);
    const float* base = g_warp + (size_t)(cam * DSLICE + d) * FH * FW * C1 + c * 4;
    for (int iy = 0; iy < ny; iy++) {
        const float* rowb = base + (size_t)(jy0 + iy) * FW * C1;
        for (int ix = 0; ix < nx; ix++) {
            float wgt = wyv[iy] * wxv[ix];
            float4 t = *(const float4*)(rowb + (size_t)(jx0 + ix) * C1);
            acc.x += wgt * t.x; acc.y += wgt * t.y;
            acc.z += wgt * t.z; acc.w += wgt * t.w;
        }
    }
    size_t obase = (((size_t)d * HO + ho) * WO + wo) * CF + cam * C1 + c * 4;
    uint32_t h0, l0, h1, l1;
    split2(acc.x, acc.y, h0, l0);
    split2(acc.z, acc.w, h1, l1);
    *(uint2*)(g_costs_h + obase) = make_uint2(h0, h1);
    *(uint2*)(g_costs_l + obase) = make_uint2(l0, l1);
}

// ---------------- K4: conv3d 3x3x3 pad1 + relu, mma.sync bf16 split ------------------------
// 128 threads / 4 warps, SINGLE-buffered A and B smem -> 2 CTAs/SM (8 warps/SM) for overlap.
// Warp tile (MI*16) x 32 from block M128 x N(32*NWN).
// conv1: MI=4, NWN=2 (warp M64xN32). conv2: MI=2, NWN=1 (warp M32xN32).
template<int CIN, int COUT, int MI, int NWN, bool OBF>
__global__ void __launch_bounds__(128)
k_conv3d_mma(const __nv_bfloat16* __restrict__ in_h, const __nv_bfloat16* __restrict__ in_l,
             const __nv_bfloat16* __restrict__ wB,
             __nv_bfloat16* __restrict__ out_h, __nv_bfloat16* __restrict__ out_l,
             float* __restrict__ out_f)
{
    constexpr int NT   = 128;
    constexpr int PK   = CIN + 8;
    constexpr int PKB  = PK * 2;             // bytes per smem row
    constexpr int SA   = 130 * PKB;          // one A plane (hi or lo)
    constexpr int TB   = 2 * COUT * PKB;     // B tap (hi + lo)
    constexpr int NJ   = (COUT / NWN) / 8;   // 4
    constexpr int KST  = CIN / 16;           // k-steps per item
    constexpr int CH   = CIN / 8;            // 16B chunks per A row per plane

    extern __shared__ char dsm[];
    const uint32_t sBase = smem_u32(dsm);
    const uint32_t sA = sBase;               // [A(hi+lo) | B(hi+lo)]
    const uint32_t sB = sBase + 2 * SA;

    int tid  = threadIdx.x;
    int wid  = tid >> 5, lane = tid & 31;
    int gid  = lane >> 2, tig = lane & 3;
    int wM   = wid / NWN;
    int wN   = wid % NWN;
    int ow0  = blockIdx.x * 128;
    int oh   = blockIdx.y, od = blockIdx.z;

    // ---- build valid (kd,kh) list ----
    int zdv[9], zhv[9], t9v[9];
    int nv = 0;
    for (int kd = 0; kd < 3; kd++) {
        int zd = od + kd - 1;
        if (zd < 0 || zd >= DSLICE) continue;
        for (int kh = 0; kh < 3; kh++) {
            int zh = oh + kh - 1;
            if (zh < 0 || zh >= HO) continue;
            zdv[nv] = zd; zhv[nv] = zh; t9v[nv] = kd * 3 + kh;
            nv++;
        }
    }
    int nitems = nv * 3;

    float acc[MI][NJ][4];
#pragma unroll
    for (int mi = 0; mi < MI; mi++)
#pragma unroll
        for (int nj = 0; nj < NJ; nj++)
#pragma unroll
            for (int cc = 0; cc < 4; cc++) acc[mi][nj][cc] = 0.f;

    auto stage_A = [&](int ai) {
        size_t inoff = ((size_t)zdv[ai] * HO + zhv[ai]) * WO * CIN;
        for (int i = tid; i < 130 * CH; i += NT) {
            int r = i / CH, g = i % CH;
            int p = ow0 - 1 + r;
            bool v = (p >= 0 && p < WO);
            int pc = v ? p : 0;
            size_t so = inoff + (size_t)pc * CIN + g * 8;
            uint32_t doff = (uint32_t)r * PKB + g * 16;
            cp_async16(sA + doff,      in_h + so, v);
            cp_async16(sA + SA + doff, in_l + so, v);
        }
    };
    auto stage_B = [&](int j) {
        int t = t9v[j / 3] * 3 + (j % 3);
        const char* src = (const char*)(wB + (size_t)t * COUT * PK * 2);
        for (int i = tid; i < TB / 16; i += NT)
            cp_async16(sB + i * 16, src + i * 16, true);
    };

    for (int j = 0; j < nitems; j++) {
        // single-buffer staging (other co-resident CTA hides this latency)
        if (j % 3 == 0) stage_A(j / 3);
        stage_B(j);
        cp_commit();
        cp_wait0();
        __syncthreads();

        int q = j % 3;
        uint32_t aB0 = sA + (uint32_t)(q + wM * (MI * 16) + gid) * PKB + tig * 4;
        uint32_t bB0 = sB + (uint32_t)(wN * 32 + gid) * PKB + tig * 4;

        // register double-buffered fragments
        uint32_t ah[2][MI][4], al[2][MI][4];
        uint32_t bh[2][NJ][2], bl[2][NJ][2];

        auto load_frags = [&](int buf, int ks) {
            uint32_t ko = (uint32_t)ks * 32;
#pragma unroll
            for (int mi = 0; mi < MI; mi++) {
                uint32_t a = aB0 + mi * 16 * PKB + ko;
                ah[buf][mi][0] = lds32(a);
                ah[buf][mi][1] = lds32(a + 8 * PKB);
                ah[buf][mi][2] = lds32(a + 16);
                ah[buf][mi][3] = lds32(a + 8 * PKB + 16);
                uint32_t b = a + SA;
                al[buf][mi][0] = lds32(b);
                al[buf][mi][1] = lds32(b + 8 * PKB);
                al[buf][mi][2] = lds32(b + 16);
                al[buf][mi][3] = lds32(b + 8 * PKB + 16);
            }
#pragma unroll
            for (int nj = 0; nj < NJ; nj++) {
                uint32_t bb = bB0 + nj * 8 * PKB + ko;
                bh[buf][nj][0] = lds32(bb);
                bh[buf][nj][1] = lds32(bb + 16);
                bl[buf][nj][0] = lds32(bb + COUT * PKB);
                bl[buf][nj][1] = lds32(bb + COUT * PKB + 16);
            }
        };

        load_frags(0, 0);
#pragma unroll
        for (int ks = 0; ks < KST; ks++) {
            int cur = ks & 1;
            if (ks + 1 < KST) load_frags(cur ^ 1, ks + 1);
            // split-outermost: consecutive mmas hit different accumulators
#pragma unroll
            for (int nj = 0; nj < NJ; nj++)
#pragma unroll
                for (int mi = 0; mi < MI; mi++)
                    mma_bf16(acc[mi][nj][0], acc[mi][nj][1], acc[mi][nj][2], acc[mi][nj][3],
                             ah[cur][mi][0], ah[cur][mi][1], ah[cur][mi][2], ah[cur][mi][3],
                             bh[cur][nj][0], bh[cur][nj][1]);
#pragma unroll
            for (int nj = 0; nj < NJ; nj++)
#pragma unroll
                for (int mi = 0; mi < MI; mi++)
                    mma_bf16(acc[mi][nj][0], acc[mi][nj][1], acc[mi][nj][2], acc[mi][nj][3],
                             ah[cur][mi][0], ah[cur][mi][1], ah[cur][mi][2], ah[cur][mi][3],
                             bl[cur][nj][0], bl[cur][nj][1]);
#pragma unroll
            for (int nj = 0; nj < NJ; nj++)
#pragma unroll
                for (int mi = 0; mi < MI; mi++)
                    mma_bf16(acc[mi][nj][0], acc[mi][nj][1], acc[mi][nj][2], acc[mi][nj][3],
                             al[cur][mi][0], al[cur][mi][1], al[cur][mi][2], al[cur][mi][3],
                             bh[cur][nj][0], bh[cur][nj][1]);
        }
        __syncthreads();
    }

    // ---- epilogue: relu + store ----
#pragma unroll
    for (int mi = 0; mi < MI; mi++) {
        int row = wM * (MI * 16) + mi * 16 + gid;
        size_t base0 = (((size_t)od * HO + oh) * WO + ow0 + row) * COUT;
        size_t base1 = base0 + 8 * COUT;      // row + 8
#pragma unroll
        for (int nj = 0; nj < NJ; nj++) {
            int col = wN * 32 + nj * 8 + tig * 2;
            float v00 = fmaxf(acc[mi][nj][0], 0.f);
            float v01 = fmaxf(acc[mi][nj][1], 0.f);
            float v10 = fmaxf(acc[mi][nj][2], 0.f);
            float v11 = fmaxf(acc[mi][nj][3], 0.f);
            if (OBF) {
                uint32_t h0, l0, h1, l1;
                split2(v00, v01, h0, l0);
                split2(v10, v11, h1, l1);
                *(uint32_t*)(out_h + base0 + col) = h0;
                *(uint32_t*)(out_l + base0 + col) = l0;
                *(uint32_t*)(out_h + base1 + col) = h1;
                *(uint32_t*)(out_l + base1 + col) = l1;
            } else {
                *(float2*)(out_f + base0 + col) = make_float2(v00, v01);
                *(float2*)(out_f + base1 + col) = make_float2(v10, v11);
            }
        }
    }
}

// ---------------- K5: conv3d 32->1 (no relu), smem-tiled ----------------
__global__ void __launch_bounds__(256)
k_reg2(const float* __restrict__ w2)
{
    __shared__ float ws_t[27 * 32];                 // [k27][ic32]
    __shared__ float tile[10][34][32];              // [zh][zw][c]
    int tx = threadIdx.x & 31;
    int ty = threadIdx.x >> 5;
    int tid = threadIdx.x;
    for (int i = tid; i < 864; i += 256) {
        int ic = i / 27, k = i % 27;
        ws_t[k * 32 + ic] = w2[i];
    }

    int ow0 = blockIdx.x * 32;
    int oh0 = blockIdx.y * 8;
    int od  = blockIdx.z;
    int ow = ow0 + tx, oh = oh0 + ty;

    float acc = 0.f;
    for (int kd = 0; kd < 3; kd++) {
        int zd = od + kd - 1;
        if (zd < 0 || zd >= DSLICE) continue;
        __syncthreads();
        for (int i = tid; i < 10 * 34 * 8; i += 256) {
            int g  = i & 7;
            int zw = (i >> 3) % 34 + ow0 - 1;
            int zh = (i >> 3) / 34 + oh0 - 1;
            bool v = (zw >= 0 && zw < WO && zh >= 0 && zh < HO);
            int zwc = v ? zw : 0, zhc = v ? zh : 0;
            const float* src = g_x2 + (((size_t)zd * HO + zhc) * WO + zwc) * C3 + g * 4;
            cp_async16(smem_u32(&tile[(i >> 3) / 34][(i >> 3) % 34][g * 4]), src, v);
        }
        cp_commit();
        cp_wait0();
        __syncthreads();

#pragma unroll
        for (int kh = 0; kh < 3; kh++) {
#pragma unroll
            for (int kw = 0; kw < 3; kw++) {
                int k = kd * 9 + kh * 3 + kw;
                const float4* p  = (const float4*)&tile[ty + kh][tx + kw][0];
                const float4* wv = (const float4*)&ws_t[k * 32];
#pragma unroll
                for (int qq = 0; qq < 8; qq++) {
                    float4 a = p[qq], b = wv[qq];
                    acc += a.x * b.x + a.y * b.y + a.z * b.z + a.w * b.w;
                }
            }
        }
    }
    g_x3[((size_t)od * HO + oh) * WO + ow] = acc;
}

// ---------------- K6: D-resize 4->8 + softmax + expectation ----------------
__global__ void k_final(float* __restrict__ outp)
{
    int pos = blockIdx.x * 256 + threadIdx.x;
    float v[4];
#pragma unroll
    for (int d = 0; d < 4; d++) v[d] = g_x3[(size_t)d * (HO * WO) + pos];

    float y[8];
#pragma unroll
    for (int o = 0; o < 8; o++) {
        float s = 0.5f * o - 0.25f;
        int j0 = max(0, (int)ceilf(s - 1.f));
        int j1 = min(3, (int)floorf(s + 1.f));
        float acc = 0.f, wsum = 0.f;
        for (int j = j0; j <= j1; j++) {
            float w = fmaxf(1.f - fabsf(s - (float)j), 0.f);
            acc += w * v[j]; wsum += w;
        }
        y[o] = acc / wsum;
    }
    float m = y[0];
#pragma unroll
    for (int o = 1; o < 8; o++) m = fmaxf(m, y[o]);
    float esum = 0.f, dsum = 0.f;
#pragma unroll
    for (int o = 0; o < 8; o++) {
        float e = expf(y[o] - m);
        esum += e;
        dsum += e * (float)o;
    }
    outp[pos] = dsum / esum;
}

// ---------------- host launch ----------------
extern "C" void kernel_launch(void* const* d_in, const int* in_sizes, int n_in,
                              void* d_out, int out_size)
{
    const float* cams[4] = { (const float*)d_in[0], (const float*)d_in[1],
                             (const float*)d_in[2], (const float*)d_in[3] };
    const float* grids    = (const float*)d_in[4];
    const float* w_feat   = (const float*)d_in[5];
    const float* w_fusion = (const float*)d_in[6];
    const float* w_reg1   = (const float*)d_in[7];
    const float* w_reg2   = (const float*)d_in[8];
    float* out = (float*)d_out;

    __nv_bfloat16 *p_wB1, *p_wB2, *p_ch, *p_cl, *p_x1h, *p_x1l;
    float* p_x2;
    cudaGetSymbolAddress((void**)&p_x2,  g_x2);
    cudaGetSymbolAddress((void**)&p_wB1, g_wB1);
    cudaGetSymbolAddress((void**)&p_wB2, g_wB2);
    cudaGetSymbolAddress((void**)&p_ch,  g_costs_h);
    cudaGetSymbolAddress((void**)&p_cl,  g_costs_l);
    cudaGetSymbolAddress((void**)&p_x1h, g_x1_h);
    cudaGetSymbolAddress((void**)&p_x1l, g_x1_l);

    // single-buffered: A(hi+lo) + B(hi+lo) -> 2 CTAs/SM
    const int SMEM1 = 2 * (130 * PK1 * 2) + 2 * C2 * PK1 * 2;   // 70720 + 34816 = 105536
    const int SMEM2 = 2 * (130 * PK2 * 2) + 2 * C3 * PK2 * 2;   // 37440 +  9216 =  46656
    cudaFuncSetAttribute((const void*)k_conv3d_mma<CF, C2, 4, 2, true>,
                         cudaFuncAttributeMaxDynamicSharedMemorySize, SMEM1);
    cudaFuncSetAttribute((const void*)k_conv3d_mma<C2, C3, 2, 1, false>,
                         cudaFuncAttributeMaxDynamicSharedMemorySize, SMEM2);

    // 1: feature extraction + weight prep (fused)
    k_feat4w<<<dim3(FW / 16, FH / 16, 5), dim3(16, 16)>>>(
        cams[0], cams[1], cams[2], cams[3], w_feat, w_fusion, w_reg1);

    // 2: plane sweep warp (2 d per thread)
    k_warp<<<dim3(FH * FW / 32, 2, CAMS), 256>>>(grids);

    // 3: antialiased resize -> bf16 hi/lo cost volume
    k_resize<<<dim3(HO * WO / 32, DSLICE, CAMS), 256>>>();

    // 4: conv1 (profiled launch)  5: conv2 — single-buffered smem, 2 CTAs/SM
    k_conv3d_mma<CF, C2, 4, 2, true ><<<dim3(WO / 128, HO, DSLICE), 128, SMEM1>>>(p_ch,  p_cl,  p_wB1, p_x1h, p_x1l, nullptr);
    k_conv3d_mma<C2, C3, 2, 1, false><<<dim3(WO / 128, HO, DSLICE), 128, SMEM2>>>(p_x1h, p_x1l, p_wB2, nullptr, nullptr, p_x2);

    // 6: squeeze conv
    k_reg2<<<dim3(WO / 32, HO / 8, DSLICE), 256>>>(w_reg2);

    // 7: disparity regression
    k_final<<<(HO * WO) / 256, 256>>>(out);
}